// round 10
// baseline (speedup 1.0000x reference)
#include <cuda_runtime.h>
#include <cstdint>

#define D         32000
#define D4        8000
#define ROW_BYTES 128000
#define THREADS   1024
#define NV4       8
#define NE        32
#define MAX_ITER  100
#define TOL       1e-5f
#define HI_OFFSET 1.9888196601125011f   // -gp(1/32000) = 2 - 2/sqrt(32000)
#define NEG_BIG   -1e30f
#define ROWS      4096

#define NB        1024
#define CAP       8
#define OVF_CAP   64
#define FIXF      1099511627776.0f       // 2^40
#define INVFIXF   9.094947017729282e-13f // 2^-40
#define Q30F      1073741824.0f          // 2^30

// dynamic smem layout (bytes), all 8-aligned
#define OFF_BUF   0
#define OFF_CNT   128000                       // NB int
#define OFF_S1    (OFF_CNT + NB * 4)           // NB ll
#define OFF_S2    (OFF_S1 + NB * 8)            // NB ll
#define OFF_SUFN  (OFF_S2 + NB * 8)            // (NB+1) int (+4 pad)
#define OFF_SUFS1 (OFF_SUFN + (NB + 1) * 4 + 4)// (NB+1) ll
#define OFF_SUFS2 (OFF_SUFS1 + (NB + 1) * 8)   // (NB+1) ll
#define OFF_VALS  (OFF_SUFS2 + (NB + 1) * 8)   // NB*CAP float
#define OFF_OVFG  (OFF_VALS + NB * CAP * 4)    // OVF_CAP float
#define OFF_OVFB  (OFF_OVFG + OVF_CAP * 4)     // OVF_CAP int
#define SMEM_DYN  (OFF_OVFB + OVF_CAP * 4)     // ~202264

__device__ __forceinline__ uint32_t smem_u32(const void* p) {
    uint32_t a;
    asm("{ .reg .u64 t; cvta.to.shared.u64 t, %1; cvt.u32.u64 %0, t; }"
        : "=r"(a) : "l"(p));
    return a;
}

__device__ __forceinline__ void mbar_init(uint32_t mbar, uint32_t count) {
    asm volatile("mbarrier.init.shared.b64 [%0], %1;" :: "r"(mbar), "r"(count) : "memory");
}

__device__ __forceinline__ void tma_prefetch_row(uint32_t dst_smem, const float* src,
                                                 uint32_t mbar) {
    asm volatile("mbarrier.arrive.expect_tx.shared.b64 _, [%0], %1;"
                 :: "r"(mbar), "r"((uint32_t)ROW_BYTES) : "memory");
    asm volatile("cp.async.bulk.shared::cta.global.mbarrier::complete_tx::bytes "
                 "[%0], [%1], %2, [%3];"
                 :: "r"(dst_smem), "l"(src), "r"((uint32_t)ROW_BYTES), "r"(mbar)
                 : "memory");
}

__device__ __forceinline__ void mbar_wait(uint32_t mbar, uint32_t phase) {
    asm volatile(
        "{\n\t"
        ".reg .pred P;\n\t"
        "W%=:\n\t"
        "mbarrier.try_wait.parity.acquire.cta.shared::cta.b64 P, [%0], %1, 0x989680;\n\t"
        "@!P bra W%=;\n\t"
        "}"
        :: "r"(mbar), "r"(phase) : "memory");
}

__device__ __forceinline__ float warp_sum(float v) {
#pragma unroll
    for (int o = 16; o; o >>= 1) v += __shfl_xor_sync(0xffffffffu, v, o);
    return v;
}

__device__ __forceinline__ float warp_max(float v) {
#pragma unroll
    for (int o = 16; o; o >>= 1) v = fmaxf(v, __shfl_xor_sync(0xffffffffu, v, o));
    return v;
}

__global__ void __launch_bounds__(THREADS, 1)
tsallis_secant_kernel(const float* __restrict__ X, float* __restrict__ Y) {
    extern __shared__ __align__(16) char smem[];
    float*      buf   = (float*)(smem + OFF_BUF);
    int*        cnt   = (int*)(smem + OFF_CNT);
    long long*  S1f   = (long long*)(smem + OFF_S1);
    long long*  S2f   = (long long*)(smem + OFF_S2);
    int*        sufN  = (int*)(smem + OFF_SUFN);
    long long*  sufS1 = (long long*)(smem + OFF_SUFS1);
    long long*  sufS2 = (long long*)(smem + OFF_SUFS2);
    float*      vals  = (float*)(smem + OFF_VALS);
    float*      ovfg  = (float*)(smem + OFF_OVFG);
    int*        ovfb  = (int*)(smem + OFF_OVFB);

    __shared__ float red[2][32];
    __shared__ long long wS1[32], wS2[32];
    __shared__ int wN[32];
    __shared__ int novf_s, fbflag_s;
    __shared__ __align__(8) unsigned long long mbar_storage;

    const int tid  = threadIdx.x;
    const int lane = tid & 31;
    const int wid  = tid >> 5;

    const uint32_t mbar    = smem_u32(&mbar_storage);
    const uint32_t buf_u32 = smem_u32(buf);

    if (tid == 0) mbar_init(mbar, 1);
    __syncthreads();

    int rb = 0;
    auto block_sum = [&](float s) -> float {   // one-sync block sum (fallback path)
        s = warp_sum(s);
        if (lane == 0) red[rb][wid] = s;
        __syncthreads();
        float t = warp_sum(red[rb][lane]);
        rb ^= 1;
        return t;
    };

    int row = blockIdx.x;
    const int stride = gridDim.x;

    if (tid == 0 && row < ROWS) {
        tma_prefetch_row(buf_u32, X + (size_t)row * D, mbar);
    }
    uint32_t phase = 0;

    for (; row < ROWS; row += stride) {
        mbar_wait(mbar, phase);
        phase ^= 1;

        // ---- SMEM -> registers, fused local max ----
        float xv[NE];
        float m = NEG_BIG;
        const float4* b4 = reinterpret_cast<const float4*>(buf);
#pragma unroll
        for (int k = 0; k < NV4; k++) {
            const int i4 = tid + k * THREADS;
            if (k < NV4 - 1 || i4 < D4) {
                float4 v = b4[i4];
                xv[4 * k + 0] = v.x;
                xv[4 * k + 1] = v.y;
                xv[4 * k + 2] = v.z;
                xv[4 * k + 3] = v.w;
            } else {
                xv[4 * k + 0] = NEG_BIG;
                xv[4 * k + 1] = NEG_BIG;
                xv[4 * k + 2] = NEG_BIG;
                xv[4 * k + 3] = NEG_BIG;
            }
        }
#pragma unroll
        for (int k = 0; k < NE; k++) m = fmaxf(m, xv[k]);

        __syncthreads();   // B1: buf consumed by all; prev row fully done

        const int nrow = row + stride;
        if (tid == 0 && nrow < ROWS) {
            tma_prefetch_row(buf_u32, X + (size_t)nrow * D, mbar);
        }

        // ---- zero tables (one bucket per thread) ----
        cnt[tid] = 0;
        S1f[tid] = 0;
        S2f[tid] = 0;
        if (tid == 0) { novf_s = 0; fbflag_s = 0; }

        // ---- block max ----
        m = warp_max(m);
        if (lane == 0) red[0][wid] = m;
        __syncthreads();   // B2: publishes zeros + max partials
        const float max_val = warp_max(red[0][lane]);

        // ---- bucket pass over actives {g > 0}, g = 1 + 0.5*(x - max) ----
        const float c0 = fmaf(-0.5f, max_val, 1.0f);
#pragma unroll
        for (int k = 0; k < NE; k++) {
            const float g = fmaf(0.5f, xv[k], c0);
            if (g > 0.0f) {
                int b = (int)(g * (float)NB);
                if (b > NB - 1) b = NB - 1;
                const int pos = atomicAdd(&cnt[b], 1);
                const long long g1 = __float2ll_rn(g * FIXF);
                const long long g2 = __float2ll_rn(g * g * FIXF);
                atomicAdd((unsigned long long*)&S1f[b], (unsigned long long)g1);
                atomicAdd((unsigned long long*)&S2f[b], (unsigned long long)g2);
                if (pos < CAP) {
                    vals[b * CAP + pos] = g;
                } else {
                    const int p2 = atomicAdd(&novf_s, 1);
                    if (p2 < OVF_CAP) { ovfg[p2] = g; ovfb[p2] = b; }
                    else fbflag_s = 1;
                }
            }
        }
        __syncthreads();   // B3: tables complete

        // ---- suffix scan (reverse inclusive) over (S1, S2, n) ----
        {
            const int r = NB - 1 - tid;
            long long a1 = S1f[r], a2 = S2f[r];
            int an = cnt[r];
#pragma unroll
            for (int o = 1; o < 32; o <<= 1) {
                long long n1 = __shfl_up_sync(0xffffffffu, a1, o);
                long long n2 = __shfl_up_sync(0xffffffffu, a2, o);
                int nn = __shfl_up_sync(0xffffffffu, an, o);
                if (lane >= o) { a1 += n1; a2 += n2; an += nn; }
            }
            if (lane == 31) { wS1[wid] = a1; wS2[wid] = a2; wN[wid] = an; }
            __syncthreads();   // B4
            if (wid == 0) {
                long long b1 = wS1[lane], b2 = wS2[lane];
                int bn = wN[lane];
                long long i1 = b1, i2 = b2;
                int in_ = bn;
#pragma unroll
                for (int o = 1; o < 32; o <<= 1) {
                    long long n1 = __shfl_up_sync(0xffffffffu, i1, o);
                    long long n2 = __shfl_up_sync(0xffffffffu, i2, o);
                    int nn = __shfl_up_sync(0xffffffffu, in_, o);
                    if (lane >= o) { i1 += n1; i2 += n2; in_ += nn; }
                }
                wS1[lane] = i1 - b1;   // exclusive warp bases
                wS2[lane] = i2 - b2;
                wN[lane]  = in_ - bn;
            }
            __syncthreads();   // B5
            a1 += wS1[wid]; a2 += wS2[wid]; an += wN[wid];
            sufS1[r] = a1; sufS2[r] = a2; sufN[r] = an;
            if (tid == 0) { sufS1[NB] = 0; sufS2[NB] = 0; sufN[NB] = 0; }
        }
        __syncthreads();   // B6: suffix tables visible

        const int fb_ovf = fbflag_s;
        const int novf = (novf_s < OVF_CAP) ? novf_s : OVF_CAP;

        // ---- barrier-free exact f(u): u = tau - max >= 0 ----
        // f = S2suf - 2q*S1suf + q^2*n + boundary - 1, all in 2^40 fixed point
        auto eval_fast = [&](float u) -> float {
            const float q = 0.5f * u;
            const int bq = (int)(q * (float)NB);
            if (bq >= NB) return -1.0f;
            const long long s1 = sufS1[bq + 1];
            const long long s2 = sufS2[bq + 1];
            const int n = sufN[bq + 1];
            long long bacc = 0;
            const int cb = cnt[bq];
            const int cs = (cb < CAP) ? cb : CAP;
            for (int j = 0; j < cs; j++) {
                const float g = vals[bq * CAP + j];
                const float h = g - q;
                if (h > 0.0f) bacc += __float2ll_rn(h * h * FIXF);
            }
            for (int j = 0; j < novf; j++) {
                if (ovfb[j] == bq) {
                    const float g = ovfg[j];
                    const float h = g - q;
                    if (h > 0.0f) bacc += __float2ll_rn(h * h * FIXF);
                }
            }
            const long long q30 = __float2ll_rn(q * Q30F);
            const long long qsq40 = (q30 * q30) >> 20;            // q^2 @2^40
            const long long t1 = (long long)(((__int128)s1 * q30) >> 29); // 2q*S1 @2^40
            const long long ffix = s2 - t1 + (long long)n * qsq40 + bacc;
            return (float)ffix * INVFIXF - 1.0f;
        };

        // ---- secant (uniform, no block barriers) ----
        bool bad = false;
        float u_hi = HI_OFFSET;
        if (!fb_ovf) {
            float u_lo = 0.0f;
            float f_lo = eval_fast(0.0f);
            float f_hi = eval_fast(HI_OFFSET);
#pragma unroll 1
            for (int it = 0; it < MAX_ITER; it++) {
                const float diff = f_lo - f_hi;
                if (diff * diff < TOL) break;
                const float ut = (u_lo * f_hi - u_hi * f_lo) / (f_hi - f_lo);
                if (!(ut >= 0.0f)) { bad = true; break; }   // overshoot / NaN
                u_lo = u_hi;
                f_lo = f_hi;
                u_hi = ut;
                f_hi = eval_fast(ut);
            }
        }

        float tau_final;
        if (fb_ovf || bad) {
            // ---- exact block-wide fallback secant (rare, uniform) ----
            auto part_full = [&](float c2) -> float {
                float a0 = 0.f, a1 = 0.f, a2 = 0.f, a3 = 0.f;
#pragma unroll
                for (int k = 0; k < NE; k += 4) {
                    float v0 = fmaxf(fmaf(xv[k + 0], 0.5f, c2), 0.0f);
                    float v1 = fmaxf(fmaf(xv[k + 1], 0.5f, c2), 0.0f);
                    float v2 = fmaxf(fmaf(xv[k + 2], 0.5f, c2), 0.0f);
                    float v3 = fmaxf(fmaf(xv[k + 3], 0.5f, c2), 0.0f);
                    a0 = fmaf(v0, v0, a0);
                    a1 = fmaf(v1, v1, a1);
                    a2 = fmaf(v2, v2, a2);
                    a3 = fmaf(v3, v3, a3);
                }
                return (a0 + a1) + (a2 + a3);
            };
            float lo = max_val, hi = max_val + HI_OFFSET;
            float f_lo = block_sum(part_full(fmaf(lo, -0.5f, 1.0f))) - 1.0f;
            float f_hi = block_sum(part_full(fmaf(hi, -0.5f, 1.0f))) - 1.0f;
#pragma unroll 1
            for (int it = 0; it < MAX_ITER; it++) {
                const float diff = f_lo - f_hi;
                if (diff * diff < TOL) break;
                const float tau = (lo * f_hi - hi * f_lo) / (f_hi - f_lo);
                lo = hi;
                f_lo = f_hi;
                hi = tau;
                f_hi = block_sum(part_full(fmaf(tau, -0.5f, 1.0f))) - 1.0f;
            }
            tau_final = hi;
        } else {
            tau_final = max_val + u_hi;
        }

        // ---- write p(X - tau_final) with streaming stores ----
        float4* y4 = reinterpret_cast<float4*>(Y) + (size_t)row * D4;
        const float c2 = fmaf(tau_final, -0.5f, 1.0f);
#pragma unroll
        for (int k = 0; k < NV4; k++) {
            const int i4 = tid + k * THREADS;
            if (k < NV4 - 1 || i4 < D4) {
                float v0 = fmaxf(fmaf(xv[4 * k + 0], 0.5f, c2), 0.0f);
                float v1 = fmaxf(fmaf(xv[4 * k + 1], 0.5f, c2), 0.0f);
                float v2 = fmaxf(fmaf(xv[4 * k + 2], 0.5f, c2), 0.0f);
                float v3 = fmaxf(fmaf(xv[4 * k + 3], 0.5f, c2), 0.0f);
                float4 r;
                r.x = v0 * v0;
                r.y = v1 * v1;
                r.z = v2 * v2;
                r.w = v3 * v3;
                __stcs(&y4[i4], r);
            }
        }
        // next row: mbar_wait then B1 fences all shared-state reuse
    }
}

extern "C" void kernel_launch(void* const* d_in, const int* in_sizes, int n_in,
                              void* d_out, int out_size) {
    const float* X = (const float*)d_in[0];
    float* Y = (float*)d_out;

    static int n_sm = 0;
    if (n_sm == 0) {
        cudaDeviceGetAttribute(&n_sm, cudaDevAttrMultiProcessorCount, 0);
        cudaFuncSetAttribute(tsallis_secant_kernel,
                             cudaFuncAttributeMaxDynamicSharedMemorySize,
                             SMEM_DYN);
    }
    tsallis_secant_kernel<<<n_sm, THREADS, SMEM_DYN>>>(X, Y);
}

// round 11
// speedup vs baseline: 1.8419x; 1.8419x over previous
#include <cuda_runtime.h>
#include <cstdint>

#define D         32000
#define D4        8000
#define ROW_BYTES 128000
#define THREADS   1024
#define NV4       8
#define NE        32
#define MAX_ITER  100
#define TOL       1e-5f
#define HI_OFFSET 1.9888196601125011f   // -gp(1/32000) = 2 - 2/sqrt(32000)
#define NEG_BIG   -1e30f
#define ROWS      4096
#define ACT_CAP   1536
#define SECW      128                   // threads 0-127: secant executors
#define ARN       12                    // ACT_CAP / SECW

__device__ __forceinline__ uint32_t smem_u32(const void* p) {
    uint32_t a;
    asm("{ .reg .u64 t; cvta.to.shared.u64 t, %1; cvt.u32.u64 %0, t; }"
        : "=r"(a) : "l"(p));
    return a;
}

__device__ __forceinline__ void mbar_init(uint32_t mbar, uint32_t count) {
    asm volatile("mbarrier.init.shared.b64 [%0], %1;" :: "r"(mbar), "r"(count) : "memory");
}

__device__ __forceinline__ void tma_prefetch_row(uint32_t dst_smem, const float* src,
                                                 uint32_t mbar) {
    asm volatile("mbarrier.arrive.expect_tx.shared.b64 _, [%0], %1;"
                 :: "r"(mbar), "r"((uint32_t)ROW_BYTES) : "memory");
    asm volatile("cp.async.bulk.shared::cta.global.mbarrier::complete_tx::bytes "
                 "[%0], [%1], %2, [%3];"
                 :: "r"(dst_smem), "l"(src), "r"((uint32_t)ROW_BYTES), "r"(mbar)
                 : "memory");
}

__device__ __forceinline__ void mbar_wait(uint32_t mbar, uint32_t phase) {
    asm volatile(
        "{\n\t"
        ".reg .pred P;\n\t"
        "W%=:\n\t"
        "mbarrier.try_wait.parity.acquire.cta.shared::cta.b64 P, [%0], %1, 0x989680;\n\t"
        "@!P bra W%=;\n\t"
        "}"
        :: "r"(mbar), "r"(phase) : "memory");
}

#define BAR_SEC() asm volatile("bar.sync 1, 128;" ::: "memory")

__device__ __forceinline__ float warp_sum(float v) {
#pragma unroll
    for (int o = 16; o; o >>= 1) v += __shfl_xor_sync(0xffffffffu, v, o);
    return v;
}

__device__ __forceinline__ float warp_max(float v) {
#pragma unroll
    for (int o = 16; o; o >>= 1) v = fmaxf(v, __shfl_xor_sync(0xffffffffu, v, o));
    return v;
}

__global__ void __launch_bounds__(THREADS, 1)
tsallis_secant_kernel(const float* __restrict__ X, float* __restrict__ Y) {
    extern __shared__ float buf[];          // D floats: TMA staging buffer
    __shared__ float act[ACT_CAP];          // compacted active elements
    __shared__ float red[2][32];            // block reduction scratch (fallback)
    __shared__ float exbuf[2][4];           // sec-warp partial exchange
    __shared__ float2 ex2[4];
    __shared__ int   iscan[32];
    __shared__ int   n_act_s;
    __shared__ float tau_s;
    __shared__ int   fb_s;
    __shared__ __align__(8) uint64_t mbar_storage;

    const int tid  = threadIdx.x;
    const int lane = tid & 31;
    const int wid  = tid >> 5;
    const bool is_sec = (tid < SECW);

    const uint32_t mbar    = smem_u32(&mbar_storage);
    const uint32_t buf_u32 = smem_u32(buf);

    if (tid == 0) mbar_init(mbar, 1);
    __syncthreads();

    int rb = 0;
    auto block_sum = [&](float s) -> float {   // one-sync block sum (fallback)
        s = warp_sum(s);
        if (lane == 0) red[rb][wid] = s;
        __syncthreads();
        float t = warp_sum(red[rb][lane]);
        rb ^= 1;
        return t;
    };

    int row = blockIdx.x;
    const int stride = gridDim.x;

    if (tid == 0 && row < ROWS) {
        tma_prefetch_row(buf_u32, X + (size_t)row * D, mbar);
    }
    uint32_t phase = 0;

    for (; row < ROWS; row += stride) {
        mbar_wait(mbar, phase);
        phase ^= 1;

        // ---- SMEM -> registers, fused local max ----
        float xv[NE];
        float m = NEG_BIG;
        const float4* b4 = reinterpret_cast<const float4*>(buf);
#pragma unroll
        for (int k = 0; k < NV4; k++) {
            const int i4 = tid + k * THREADS;
            if (k < NV4 - 1 || i4 < D4) {
                float4 v = b4[i4];
                xv[4 * k + 0] = v.x;
                xv[4 * k + 1] = v.y;
                xv[4 * k + 2] = v.z;
                xv[4 * k + 3] = v.w;
            } else {
                xv[4 * k + 0] = NEG_BIG;
                xv[4 * k + 1] = NEG_BIG;
                xv[4 * k + 2] = NEG_BIG;
                xv[4 * k + 3] = NEG_BIG;
            }
        }
#pragma unroll
        for (int k = 0; k < NE; k++) m = fmaxf(m, xv[k]);

        __syncthreads();   // B1: buf consumed; prev-row shared state dead

        const int nrow = row + stride;
        if (tid == 0 && nrow < ROWS) {
            tma_prefetch_row(buf_u32, X + (size_t)nrow * D, mbar);
        }

        // ---- block max ----
        m = warp_max(m);
        if (lane == 0) red[0][wid] = m;
        __syncthreads();   // B2
        const float max_val = warp_max(red[0][lane]);

        // ---- deterministic index-ordered scan compaction of {x > max-2} ----
        const float thr = max_val - 2.0f;
        int cnt = 0;
#pragma unroll
        for (int k = 0; k < NE; k++) cnt += (xv[k] > thr) ? 1 : 0;

        int inc = cnt;
#pragma unroll
        for (int o = 1; o < 32; o <<= 1) {
            int n = __shfl_up_sync(0xffffffffu, inc, o);
            if (lane >= o) inc += n;
        }
        if (lane == 31) iscan[wid] = inc;
        __syncthreads();   // B3
        if (wid == 0) {
            int v = iscan[lane];
            int iv = v;
#pragma unroll
            for (int o = 1; o < 32; o <<= 1) {
                int n = __shfl_up_sync(0xffffffffu, iv, o);
                if (lane >= o) iv += n;
            }
            iscan[lane] = iv - v;            // exclusive warp bases
            if (lane == 31) n_act_s = iv;    // total
        }
        __syncthreads();   // B4
        {
            int pos = iscan[wid] + (inc - cnt);
#pragma unroll
            for (int k = 0; k < NE; k++) {
                if (xv[k] > thr) {
                    if (pos < ACT_CAP) act[pos] = xv[k];
                    pos++;
                }
            }
        }
        __syncthreads();   // B5: act[] + n_act visible
        const int n_act = n_act_s;

        const float lo0 = max_val;                 // gp(1.0) = 0
        const float hi0 = max_val + HI_OFFSET;

        // ---- 4-warp register-resident secant (threads 0-127 only) ----
        if (is_sec) {
            int fb = (n_act > ACT_CAP) ? 1 : 0;
            float hi = hi0;
            if (!fb) {
                float ar[ARN];
#pragma unroll
                for (int j = 0; j < ARN; j++) {
                    const int i = j * SECW + tid;
                    ar[j] = (i < n_act) ? act[i] : NEG_BIG;
                }
                // fused dual initial eval (lo0, hi0 >= max_val: set exact)
                const float cl = fmaf(lo0, -0.5f, 1.0f);
                const float ch = fmaf(hi0, -0.5f, 1.0f);
                float a = 0.0f, b = 0.0f;
#pragma unroll
                for (int j = 0; j < ARN; j++) {
                    float v = fmaxf(fmaf(ar[j], 0.5f, cl), 0.0f);
                    float w = fmaxf(fmaf(ar[j], 0.5f, ch), 0.0f);
                    a = fmaf(v, v, a);
                    b = fmaf(w, w, b);
                }
                a = warp_sum(a);
                b = warp_sum(b);
                if (lane == 0) ex2[wid] = make_float2(a, b);
                BAR_SEC();
                float f_lo = ((ex2[0].x + ex2[1].x) + (ex2[2].x + ex2[3].x)) - 1.0f;
                float f_hi = ((ex2[0].y + ex2[1].y) + (ex2[2].y + ex2[3].y)) - 1.0f;
                float lo = lo0;
                int eb = 0;

#pragma unroll 1
                for (int it = 0; it < MAX_ITER; it++) {
                    const float diff = f_lo - f_hi;
                    if (diff * diff < TOL) break;
                    const float tau = (lo * f_hi - hi * f_lo) / (f_hi - f_lo);
                    if (!(tau >= max_val)) { fb = 1; break; }  // overshoot / NaN
                    lo = hi;
                    f_lo = f_hi;
                    hi = tau;
                    const float c2 = fmaf(tau, -0.5f, 1.0f);
                    float s = 0.0f;
#pragma unroll
                    for (int j = 0; j < ARN; j++) {
                        float v = fmaxf(fmaf(ar[j], 0.5f, c2), 0.0f);
                        s = fmaf(v, v, s);
                    }
                    s = warp_sum(s);
                    if (lane == 0) exbuf[eb][wid] = s;
                    BAR_SEC();
                    f_hi = ((exbuf[eb][0] + exbuf[eb][1]) +
                            (exbuf[eb][2] + exbuf[eb][3])) - 1.0f;
                    eb ^= 1;
                }
            }
            if (tid == 0) { tau_s = hi; fb_s = fb; }
        }
        __syncthreads();   // B6: tau/fb published; idle warps waited here

        float tau_final;
        if (fb_s) {
            // ---- rare exact fallback: block-wide secant over full row ----
            auto part_full = [&](float c2) -> float {
                float a0 = 0.f, a1 = 0.f, a2 = 0.f, a3 = 0.f;
#pragma unroll
                for (int k = 0; k < NE; k += 4) {
                    float v0 = fmaxf(fmaf(xv[k + 0], 0.5f, c2), 0.0f);
                    float v1 = fmaxf(fmaf(xv[k + 1], 0.5f, c2), 0.0f);
                    float v2 = fmaxf(fmaf(xv[k + 2], 0.5f, c2), 0.0f);
                    float v3 = fmaxf(fmaf(xv[k + 3], 0.5f, c2), 0.0f);
                    a0 = fmaf(v0, v0, a0);
                    a1 = fmaf(v1, v1, a1);
                    a2 = fmaf(v2, v2, a2);
                    a3 = fmaf(v3, v3, a3);
                }
                return (a0 + a1) + (a2 + a3);
            };
            float lo = lo0, hi = hi0;
            float f_lo = block_sum(part_full(fmaf(lo, -0.5f, 1.0f))) - 1.0f;
            float f_hi = block_sum(part_full(fmaf(hi, -0.5f, 1.0f))) - 1.0f;
#pragma unroll 1
            for (int it = 0; it < MAX_ITER; it++) {
                const float diff = f_lo - f_hi;
                if (diff * diff < TOL) break;
                const float tau = (lo * f_hi - hi * f_lo) / (f_hi - f_lo);
                lo = hi;
                f_lo = f_hi;
                hi = tau;
                f_hi = block_sum(part_full(fmaf(tau, -0.5f, 1.0f))) - 1.0f;
            }
            tau_final = hi;
        } else {
            tau_final = tau_s;
        }

        // ---- write p(X - tau_final) with streaming stores ----
        float4* y4 = reinterpret_cast<float4*>(Y) + (size_t)row * D4;
        const float c2 = fmaf(tau_final, -0.5f, 1.0f);
#pragma unroll
        for (int k = 0; k < NV4; k++) {
            const int i4 = tid + k * THREADS;
            if (k < NV4 - 1 || i4 < D4) {
                float v0 = fmaxf(fmaf(xv[4 * k + 0], 0.5f, c2), 0.0f);
                float v1 = fmaxf(fmaf(xv[4 * k + 1], 0.5f, c2), 0.0f);
                float v2 = fmaxf(fmaf(xv[4 * k + 2], 0.5f, c2), 0.0f);
                float v3 = fmaxf(fmaf(xv[4 * k + 3], 0.5f, c2), 0.0f);
                float4 r;
                r.x = v0 * v0;
                r.y = v1 * v1;
                r.z = v2 * v2;
                r.w = v3 * v3;
                __stcs(&y4[i4], r);
            }
        }
        // next row: mbar_wait then B1 fences shared-state reuse
    }
}

extern "C" void kernel_launch(void* const* d_in, const int* in_sizes, int n_in,
                              void* d_out, int out_size) {
    const float* X = (const float*)d_in[0];
    float* Y = (float*)d_out;

    static int n_sm = 0;
    if (n_sm == 0) {
        cudaDeviceGetAttribute(&n_sm, cudaDevAttrMultiProcessorCount, 0);
        cudaFuncSetAttribute(tsallis_secant_kernel,
                             cudaFuncAttributeMaxDynamicSharedMemorySize,
                             ROW_BYTES);
    }
    tsallis_secant_kernel<<<n_sm, THREADS, ROW_BYTES>>>(X, Y);
}

// round 12
// speedup vs baseline: 2.1612x; 1.1734x over previous
#include <cuda_runtime.h>
#include <cstdint>

#define D         32000
#define D4        8000
#define ROW_BYTES 128000
#define THREADS   1024
#define NV4       8
#define NE        32
#define MAX_ITER  100
#define TOL       1e-5f
#define HI_OFFSET 1.9888196601125011f   // -gp(1/32000) = 2 - 2/sqrt(32000)
#define NEG_BIG   -1e30f
#define ROWS      4096
#define FIXF      1099511627776.0f       // 2^40
#define INVFIXF   9.094947017729282e-13f // 2^-40

__device__ __forceinline__ uint32_t smem_u32(const void* p) {
    uint32_t a;
    asm("{ .reg .u64 t; cvta.to.shared.u64 t, %1; cvt.u32.u64 %0, t; }"
        : "=r"(a) : "l"(p));
    return a;
}

__device__ __forceinline__ void mbar_init(uint32_t mbar, uint32_t count) {
    asm volatile("mbarrier.init.shared.b64 [%0], %1;" :: "r"(mbar), "r"(count) : "memory");
}

__device__ __forceinline__ void tma_prefetch_row(uint32_t dst_smem, const float* src,
                                                 uint32_t mbar) {
    asm volatile("mbarrier.arrive.expect_tx.shared.b64 _, [%0], %1;"
                 :: "r"(mbar), "r"((uint32_t)ROW_BYTES) : "memory");
    asm volatile("cp.async.bulk.shared::cta.global.mbarrier::complete_tx::bytes "
                 "[%0], [%1], %2, [%3];"
                 :: "r"(dst_smem), "l"(src), "r"((uint32_t)ROW_BYTES), "r"(mbar)
                 : "memory");
}

__device__ __forceinline__ void mbar_wait(uint32_t mbar, uint32_t phase) {
    asm volatile(
        "{\n\t"
        ".reg .pred P;\n\t"
        "W%=:\n\t"
        "mbarrier.try_wait.parity.acquire.cta.shared::cta.b64 P, [%0], %1, 0x989680;\n\t"
        "@!P bra W%=;\n\t"
        "}"
        :: "r"(mbar), "r"(phase) : "memory");
}

__device__ __forceinline__ float warp_sum(float v) {
#pragma unroll
    for (int o = 16; o; o >>= 1) v += __shfl_xor_sync(0xffffffffu, v, o);
    return v;
}

__device__ __forceinline__ float warp_max(float v) {
#pragma unroll
    for (int o = 16; o; o >>= 1) v = fmaxf(v, __shfl_xor_sync(0xffffffffu, v, o));
    return v;
}

// monotonic float <-> u32 key (no NaNs in data)
__device__ __forceinline__ unsigned fkey(float x) {
    unsigned u = __float_as_uint(x);
    return (u & 0x80000000u) ? ~u : (u | 0x80000000u);
}
__device__ __forceinline__ float funkey(unsigned k) {
    unsigned u = (k & 0x80000000u) ? (k & 0x7fffffffu) : ~k;
    return __uint_as_float(u);
}

__global__ void __launch_bounds__(THREADS, 1)
tsallis_secant_kernel(const float* __restrict__ X, float* __restrict__ Y) {
    extern __shared__ float buf[];                  // D floats: TMA staging
    __shared__ unsigned maxkey[2];                  // parity-buffered block max
    __shared__ unsigned long long ia[4];            // parity-buffered dual-init sums
    __shared__ unsigned long long S[3];             // rotating per-eval sums
    __shared__ __align__(8) uint64_t mbar_storage;

    const int tid  = threadIdx.x;
    const int lane = tid & 31;

    const uint32_t mbar    = smem_u32(&mbar_storage);
    const uint32_t buf_u32 = smem_u32(buf);

    if (tid == 0) {
        mbar_init(mbar, 1);
        maxkey[0] = 0; maxkey[1] = 0;
        ia[0] = 0; ia[1] = 0; ia[2] = 0; ia[3] = 0;
        S[0] = 0; S[1] = 0; S[2] = 0;
    }
    __syncthreads();

    int row = blockIdx.x;
    const int stride = gridDim.x;
    int pr = 0;                                     // row parity (uniform)

    if (tid == 0 && row < ROWS) {
        tma_prefetch_row(buf_u32, X + (size_t)row * D, mbar);
    }
    uint32_t phase = 0;

    for (; row < ROWS; row += stride) {
        mbar_wait(mbar, phase);
        phase ^= 1;

        // ---- SMEM -> registers, fused local max ----
        float xv[NE];
        float m = NEG_BIG;
        const float4* b4 = reinterpret_cast<const float4*>(buf);
#pragma unroll
        for (int k = 0; k < NV4; k++) {
            const int i4 = tid + k * THREADS;
            if (k < NV4 - 1 || i4 < D4) {
                float4 v = b4[i4];
                xv[4 * k + 0] = v.x;
                xv[4 * k + 1] = v.y;
                xv[4 * k + 2] = v.z;
                xv[4 * k + 3] = v.w;
            } else {
                xv[4 * k + 0] = NEG_BIG;
                xv[4 * k + 1] = NEG_BIG;
                xv[4 * k + 2] = NEG_BIG;
                xv[4 * k + 3] = NEG_BIG;
            }
        }
#pragma unroll
        for (int k = 0; k < NE; k++) m = fmaxf(m, xv[k]);

        __syncthreads();   // B1: buf consumed; orders prev-row slot reads

        const int nrow = row + stride;
        if (tid == 0 && nrow < ROWS) {
            tma_prefetch_row(buf_u32, X + (size_t)nrow * D, mbar);
        }

        // ---- block max: warp shfl + one u32 atomicMax ----
        m = warp_max(m);
        if (lane == 0) atomicMax(&maxkey[pr], fkey(m));
        __syncthreads();   // B2
        const float max_val = funkey(maxkey[pr]);

        // ---- per-thread register pack of active set {x > max-2} ----
        const float thr = max_val - 2.0f;
        float pk0 = NEG_BIG, pk1 = NEG_BIG, pk2 = NEG_BIG, pk3 = NEG_BIG;
        int c = 0;
#pragma unroll
        for (int k = 0; k < NE; k++) {
            float x = xv[k];
            if (x > thr) {
                if      (c == 0) pk0 = x;
                else if (c == 1) pk1 = x;
                else if (c == 2) pk2 = x;
                else if (c == 3) pk3 = x;
                c++;
            }
        }
        const bool full = (c > 4);          // rare per-thread fallback

        // full-row partial sum for one tau (this thread's 32 elements)
        auto part_full = [&](float c2) -> float {
            float a0 = 0.f, a1 = 0.f, a2 = 0.f, a3 = 0.f;
#pragma unroll
            for (int k = 0; k < NE; k += 4) {
                float v0 = fmaxf(fmaf(xv[k + 0], 0.5f, c2), 0.0f);
                float v1 = fmaxf(fmaf(xv[k + 1], 0.5f, c2), 0.0f);
                float v2 = fmaxf(fmaf(xv[k + 2], 0.5f, c2), 0.0f);
                float v3 = fmaxf(fmaf(xv[k + 3], 0.5f, c2), 0.0f);
                a0 = fmaf(v0, v0, a0);
                a1 = fmaf(v1, v1, a1);
                a2 = fmaf(v2, v2, a2);
                a3 = fmaf(v3, v3, a3);
            }
            return (a0 + a1) + (a2 + a3);
        };

        // packed partial (valid when tau >= max_val and !full)
        auto part_packed = [&](float c2) -> float {
            float v0 = fmaxf(fmaf(pk0, 0.5f, c2), 0.0f);
            float v1 = fmaxf(fmaf(pk1, 0.5f, c2), 0.0f);
            float v2 = fmaxf(fmaf(pk2, 0.5f, c2), 0.0f);
            float v3 = fmaxf(fmaf(pk3, 0.5f, c2), 0.0f);
            return fmaf(v0, v0, fmaf(v1, v1, fmaf(v2, v2, v3 * v3)));
        };

        // ---- fused dual init eval: one atomic round for f(lo0), f(hi0) ----
        const float lo0 = max_val;                 // gp(1.0) = 0
        const float hi0 = max_val + HI_OFFSET;
        float f_lo, f_hi;
        {
            const float cl = fmaf(lo0, -0.5f, 1.0f);
            const float ch = fmaf(hi0, -0.5f, 1.0f);
            float a, b;
            if (full) { a = part_full(cl); b = part_full(ch); }
            else      { a = part_packed(cl); b = part_packed(ch); }
            a = warp_sum(a);
            b = warp_sum(b);
            if (lane == 0) {
                atomicAdd(&ia[2 * pr + 0], (unsigned long long)__float2ll_rn(a * FIXF));
                atomicAdd(&ia[2 * pr + 1], (unsigned long long)__float2ll_rn(b * FIXF));
            }
            if (tid == 0) {   // pre-B3: zero next row's slots (parity-separated)
                maxkey[pr ^ 1] = 0;
                ia[2 * (pr ^ 1) + 0] = 0;
                ia[2 * (pr ^ 1) + 1] = 0;
                S[0] = 0; S[1] = 0; S[2] = 0;   // prev-row reads fenced by B1
            }
            __syncthreads();   // B3
            f_lo = (float)(long long)ia[2 * pr + 0] * INVFIXF - 1.0f;
            f_hi = (float)(long long)ia[2 * pr + 1] * INVFIXF - 1.0f;
        }

        // ---- secant with early exit; eval = warp shfl + one u64 atomic ----
        float lo = lo0, hi = hi0;
        int rot = 0;                                // uniform rotation 0..2
#pragma unroll 1
        for (int it = 0; it < MAX_ITER; it++) {
            const float diff = f_lo - f_hi;
            if (diff * diff < TOL) break;
            const float tau = (lo * f_hi - hi * f_lo) / (f_hi - f_lo);
            lo = hi;
            f_lo = f_hi;
            hi = tau;

            const float c2 = fmaf(tau, -0.5f, 1.0f);
            float s;
            if (tau >= max_val) s = full ? part_full(c2) : part_packed(c2);
            else                s = part_full(c2);   // exact left-overshoot path
            s = warp_sum(s);
            if (lane == 0)
                atomicAdd(&S[rot], (unsigned long long)__float2ll_rn(s * FIXF));
            if (tid == 0) S[(rot + 1) % 3] = 0;      // 2-rounds-ahead slot
            __syncthreads();
            f_hi = (float)(long long)S[rot] * INVFIXF - 1.0f;
            rot = (rot + 1) % 3;
        }
        const float tau_final = hi;

        // ---- write p(X - tau_final) with streaming stores ----
        float4* y4 = reinterpret_cast<float4*>(Y) + (size_t)row * D4;
        const float c2 = fmaf(tau_final, -0.5f, 1.0f);
#pragma unroll
        for (int k = 0; k < NV4; k++) {
            const int i4 = tid + k * THREADS;
            if (k < NV4 - 1 || i4 < D4) {
                float v0 = fmaxf(fmaf(xv[4 * k + 0], 0.5f, c2), 0.0f);
                float v1 = fmaxf(fmaf(xv[4 * k + 1], 0.5f, c2), 0.0f);
                float v2 = fmaxf(fmaf(xv[4 * k + 2], 0.5f, c2), 0.0f);
                float v3 = fmaxf(fmaf(xv[4 * k + 3], 0.5f, c2), 0.0f);
                float4 r;
                r.x = v0 * v0;
                r.y = v1 * v1;
                r.z = v2 * v2;
                r.w = v3 * v3;
                __stcs(&y4[i4], r);
            }
        }
        pr ^= 1;
        // next row: mbar_wait + B1 fence order all shared-slot reuse
    }
}

extern "C" void kernel_launch(void* const* d_in, const int* in_sizes, int n_in,
                              void* d_out, int out_size) {
    const float* X = (const float*)d_in[0];
    float* Y = (float*)d_out;

    static int n_sm = 0;
    if (n_sm == 0) {
        cudaDeviceGetAttribute(&n_sm, cudaDevAttrMultiProcessorCount, 0);
        cudaFuncSetAttribute(tsallis_secant_kernel,
                             cudaFuncAttributeMaxDynamicSharedMemorySize,
                             ROW_BYTES);
    }
    tsallis_secant_kernel<<<n_sm, THREADS, ROW_BYTES>>>(X, Y);
}

// round 14
// speedup vs baseline: 2.6326x; 1.2181x over previous
#include <cuda_runtime.h>
#include <cstdint>

#define D         32000
#define D4        8000
#define ROW_BYTES 128000
#define THREADS   1024
#define NV4       8
#define NE        32
#define MAX_ITER  100
#define TOL       1e-5f
#define HI_OFFSET 1.9888196601125011f   // -gp(1/32000) = 2 - 2/sqrt(32000)
#define NEG_BIG   -1e30f
#define ROWS      4096
#define FIXS      2097152.0f            // 2^21
#define INVFIXS   4.76837158203125e-7f  // 2^-21

__device__ __forceinline__ uint32_t smem_u32(const void* p) {
    uint32_t a;
    asm("{ .reg .u64 t; cvta.to.shared.u64 t, %1; cvt.u32.u64 %0, t; }"
        : "=r"(a) : "l"(p));
    return a;
}

__device__ __forceinline__ void mbar_init(uint32_t mbar, uint32_t count) {
    asm volatile("mbarrier.init.shared.b64 [%0], %1;" :: "r"(mbar), "r"(count) : "memory");
}

__device__ __forceinline__ void tma_prefetch_row(uint32_t dst_smem, const float* src,
                                                 uint32_t mbar) {
    asm volatile("mbarrier.arrive.expect_tx.shared.b64 _, [%0], %1;"
                 :: "r"(mbar), "r"((uint32_t)ROW_BYTES) : "memory");
    asm volatile("cp.async.bulk.shared::cta.global.mbarrier::complete_tx::bytes "
                 "[%0], [%1], %2, [%3];"
                 :: "r"(dst_smem), "l"(src), "r"((uint32_t)ROW_BYTES), "r"(mbar)
                 : "memory");
}

__device__ __forceinline__ void mbar_wait(uint32_t mbar, uint32_t phase) {
    asm volatile(
        "{\n\t"
        ".reg .pred P;\n\t"
        "W%=:\n\t"
        "mbarrier.try_wait.parity.acquire.cta.shared::cta.b64 P, [%0], %1, 0x989680;\n\t"
        "@!P bra W%=;\n\t"
        "}"
        :: "r"(mbar), "r"(phase) : "memory");
}

// HW warp reductions (sm_80+): single REDUX instruction
__device__ __forceinline__ int redux_add_s32(int v) {
    int r;
    asm volatile("redux.sync.add.s32 %0, %1, 0xffffffff;" : "=r"(r) : "r"(v));
    return r;
}
__device__ __forceinline__ unsigned redux_max_u32(unsigned v) {
    unsigned r;
    asm volatile("redux.sync.max.u32 %0, %1, 0xffffffff;" : "=r"(r) : "r"(v));
    return r;
}

__device__ __forceinline__ float warp_sum(float v) {
#pragma unroll
    for (int o = 16; o; o >>= 1) v += __shfl_xor_sync(0xffffffffu, v, o);
    return v;
}

// monotonic float <-> u32 key (no NaNs in data)
__device__ __forceinline__ unsigned fkey(float x) {
    unsigned u = __float_as_uint(x);
    return (u & 0x80000000u) ? ~u : (u | 0x80000000u);
}
__device__ __forceinline__ float funkey(unsigned k) {
    unsigned u = (k & 0x80000000u) ? (k & 0x7fffffffu) : ~k;
    return __uint_as_float(u);
}

__global__ void __launch_bounds__(THREADS, 1)
tsallis_secant_kernel(const float* __restrict__ X, float* __restrict__ Y) {
    extern __shared__ float buf[];          // D floats: TMA staging buffer
    __shared__ int   ired[2][32];           // double-buffered fixed-point partials
    __shared__ int2  ired2[32];
    __shared__ unsigned mred[32];
    __shared__ float fred[2][32];           // float scratch (rare fallback path)
    __shared__ __align__(8) uint64_t mbar_storage;

    const int tid  = threadIdx.x;
    const int lane = tid & 31;
    const int wid  = tid >> 5;

    const uint32_t mbar    = smem_u32(&mbar_storage);
    const uint32_t buf_u32 = smem_u32(buf);

    if (tid == 0) mbar_init(mbar, 1);
    __syncthreads();

    int rb = 0;  // reduction buffer toggle (uniform across threads)

    // fast block sum via integer REDUX (deterministic fixed point)
    auto block_sum_fix = [&](float s) -> float {
        int si = __float2int_rn(s * FIXS);
        si = redux_add_s32(si);
        if (lane == 0) ired[rb][wid] = si;
        __syncthreads();
        int t = redux_add_s32(ired[rb][lane]);
        rb ^= 1;
        return (float)t * INVFIXS;
    };

    // float shfl block sum (exact path for rare left-overshoot evals)
    auto block_sum_f = [&](float s) -> float {
        s = warp_sum(s);
        if (lane == 0) fred[rb][wid] = s;
        __syncthreads();
        float t = warp_sum(fred[rb][lane]);
        rb ^= 1;
        return t;
    };

    int row = blockIdx.x;
    const int stride = gridDim.x;

    if (tid == 0 && row < ROWS) {
        tma_prefetch_row(buf_u32, X + (size_t)row * D, mbar);
    }
    uint32_t phase = 0;

    for (; row < ROWS; row += stride) {
        mbar_wait(mbar, phase);
        phase ^= 1;

        // ---- SMEM -> registers, fused local max ----
        float xv[NE];
        float m = NEG_BIG;
        const float4* b4 = reinterpret_cast<const float4*>(buf);
#pragma unroll
        for (int k = 0; k < NV4; k++) {
            const int i4 = tid + k * THREADS;
            if (k < NV4 - 1 || i4 < D4) {
                float4 v = b4[i4];
                xv[4 * k + 0] = v.x;
                xv[4 * k + 1] = v.y;
                xv[4 * k + 2] = v.z;
                xv[4 * k + 3] = v.w;
            } else {
                xv[4 * k + 0] = NEG_BIG;
                xv[4 * k + 1] = NEG_BIG;
                xv[4 * k + 2] = NEG_BIG;
                xv[4 * k + 3] = NEG_BIG;
            }
        }
#pragma unroll
        for (int k = 0; k < NE; k++) m = fmaxf(m, xv[k]);

        __syncthreads();   // all threads done reading buf

        // ---- kick prefetch of next row (overlaps everything below) ----
        const int nrow = row + stride;
        if (tid == 0 && nrow < ROWS) {
            tma_prefetch_row(buf_u32, X + (size_t)nrow * D, mbar);
        }

        // ---- block max via REDUX.max.u32 on monotonic keys ----
        unsigned mk = redux_max_u32(fkey(m));
        if (lane == 0) mred[wid] = mk;
        __syncthreads();
        const float max_val = funkey(redux_max_u32(mred[lane]));

        // ---- per-thread register pack of active set {x > max-2} ----
        const float thr = max_val - 2.0f;
        float pk0 = NEG_BIG, pk1 = NEG_BIG, pk2 = NEG_BIG, pk3 = NEG_BIG;
        int c = 0;
#pragma unroll
        for (int k = 0; k < NE; k++) {
            float x = xv[k];
            if (x > thr) {
                if      (c == 0) pk0 = x;
                else if (c == 1) pk1 = x;
                else if (c == 2) pk2 = x;
                else if (c == 3) pk3 = x;
                c++;
            }
        }
        const bool full = (c > 4);          // rare per-thread fallback

        // full-row partial sum for one tau (this thread's 32 elements)
        auto part_full = [&](float c2) -> float {
            float a0 = 0.f, a1 = 0.f, a2 = 0.f, a3 = 0.f;
#pragma unroll
            for (int k = 0; k < NE; k += 4) {
                float v0 = fmaxf(fmaf(xv[k + 0], 0.5f, c2), 0.0f);
                float v1 = fmaxf(fmaf(xv[k + 1], 0.5f, c2), 0.0f);
                float v2 = fmaxf(fmaf(xv[k + 2], 0.5f, c2), 0.0f);
                float v3 = fmaxf(fmaf(xv[k + 3], 0.5f, c2), 0.0f);
                a0 = fmaf(v0, v0, a0);
                a1 = fmaf(v1, v1, a1);
                a2 = fmaf(v2, v2, a2);
                a3 = fmaf(v3, v3, a3);
            }
            return (a0 + a1) + (a2 + a3);
        };

        // packed partial (valid when tau >= max_val and !full)
        auto part_packed = [&](float c2) -> float {
            float v0 = fmaxf(fmaf(pk0, 0.5f, c2), 0.0f);
            float v1 = fmaxf(fmaf(pk1, 0.5f, c2), 0.0f);
            float v2 = fmaxf(fmaf(pk2, 0.5f, c2), 0.0f);
            float v3 = fmaxf(fmaf(pk3, 0.5f, c2), 0.0f);
            return fmaf(v0, v0, fmaf(v1, v1, fmaf(v2, v2, v3 * v3)));
        };

        // exact f(tau) for ANY tau (uniform branch on tau)
        auto eval = [&](float tau) -> float {
            const float c2 = fmaf(tau, -0.5f, 1.0f);
            if (tau >= max_val) {
                float a = full ? part_full(c2) : part_packed(c2);
                return block_sum_fix(a);        // fast REDUX path
            } else {
                return block_sum_f(part_full(c2)); // rare exact float path
            }
        };

        // ---- fused initial evals (both taus >= max_val by construction) ----
        float lo = max_val;                 // gp(1.0) = 0
        float hi = max_val + HI_OFFSET;
        float f_lo, f_hi;
        {
            const float cl = fmaf(lo, -0.5f, 1.0f);
            const float ch = fmaf(hi, -0.5f, 1.0f);
            float a, b;
            if (full) { a = part_full(cl); b = part_full(ch); }
            else      { a = part_packed(cl); b = part_packed(ch); }
            int sa = redux_add_s32(__float2int_rn(a * FIXS));
            int sb = redux_add_s32(__float2int_rn(b * FIXS));
            if (lane == 0) ired2[wid] = make_int2(sa, sb);
            __syncthreads();
            int2 t = ired2[lane];
            f_lo = (float)redux_add_s32(t.x) * INVFIXS - 1.0f;
            f_hi = (float)redux_add_s32(t.y) * INVFIXS - 1.0f;
        }

        // ---- secant with early exit ----
#pragma unroll 1
        for (int it = 0; it < MAX_ITER; it++) {
            const float diff = f_lo - f_hi;
            if (diff * diff < TOL) break;
            const float tau = (lo * f_hi - hi * f_lo) / (f_hi - f_lo);
            lo = hi;
            f_lo = f_hi;
            hi = tau;
            f_hi = eval(hi) - 1.0f;
        }
        const float tau_final = hi;

        // ---- write p(X - tau_final) with streaming stores ----
        float4* y4 = reinterpret_cast<float4*>(Y) + (size_t)row * D4;
        const float c2 = fmaf(tau_final, -0.5f, 1.0f);
#pragma unroll
        for (int k = 0; k < NV4; k++) {
            const int i4 = tid + k * THREADS;
            if (k < NV4 - 1 || i4 < D4) {
                float v0 = fmaxf(fmaf(xv[4 * k + 0], 0.5f, c2), 0.0f);
                float v1 = fmaxf(fmaf(xv[4 * k + 1], 0.5f, c2), 0.0f);
                float v2 = fmaxf(fmaf(xv[4 * k + 2], 0.5f, c2), 0.0f);
                float v3 = fmaxf(fmaf(xv[4 * k + 3], 0.5f, c2), 0.0f);
                float4 r;
                r.x = v0 * v0;
                r.y = v1 * v1;
                r.z = v2 * v2;
                r.w = v3 * v3;
                __stcs(&y4[i4], r);
            }
        }
        __syncthreads();   // reduction-scratch reuse fence before next row
    }
}

extern "C" void kernel_launch(void* const* d_in, const int* in_sizes, int n_in,
                              void* d_out, int out_size) {
    const float* X = (const float*)d_in[0];
    float* Y = (float*)d_out;

    static int n_sm = 0;
    if (n_sm == 0) {
        cudaDeviceGetAttribute(&n_sm, cudaDevAttrMultiProcessorCount, 0);
        cudaFuncSetAttribute(tsallis_secant_kernel,
                             cudaFuncAttributeMaxDynamicSharedMemorySize,
                             ROW_BYTES);
    }
    tsallis_secant_kernel<<<n_sm, THREADS, ROW_BYTES>>>(X, Y);
}